// round 1
// baseline (speedup 1.0000x reference)
#include <cuda_runtime.h>
#include <math.h>

// ---------------- problem constants ----------------
#define BG   256                 // graphs
#define NPG  256                 // nodes per graph
#define NN   (BG*NPG)            // 65536 nodes
#define EE   (NN*16)             // 1048576 edges
#define KK   25                  // 5x5 spline kernels
#define F1   32
#define F2   64
#define F3   128
#define NC1  (BG*64)             // 16384 pool-1 clusters (8x8 grid)
#define NC2  (BG*16)             // 4096  pool-2 clusters (4x4 grid)
#define BM1W (BG*4096/32)        // bitmap words pool1 (graph x 64 x 64 pairs)
#define BM2W (BG*256/32)         // bitmap words pool2 (graph x 16 x 16 pairs)
#define E3CAP 65536              // >= 256*16*15 unique pool-2 edges

// ---------------- device scratch (static, no runtime alloc) ----------------
__device__ float    d_m[4];
__device__ int      d_ecnt1[1];
__device__ int      d_ecnt2[1];
__device__ float    d_acc1[NN*KK];
__device__ float    d_deg1[NN];
__device__ float    d_h1[NN*F1];
__device__ float    d_x2[NC1*F1];
__device__ float    d_cnt1[NC1];
__device__ float    d_pos2[NC1*2];
__device__ int      d_er2[EE];
__device__ int      d_ec2[EE];
__device__ unsigned d_bm1[BM1W];
__device__ float    d_acc2[NC1*KK*F1];
__device__ float    d_deg2[NC1];
__device__ float    d_h2[NC1*F2];
__device__ float    d_x3[NC2*F2];
__device__ float    d_cnt2[NC2];
__device__ float    d_pos3[NC2*2];
__device__ int      d_er3[E3CAP];
__device__ int      d_ec3[E3CAP];
__device__ unsigned d_bm2[BM2W];
__device__ float    d_acc3[NC2*KK*F2];
__device__ float    d_deg3[NC2];
__device__ float    d_h3[NC2*F3];

// ---------------- helpers ----------------
__device__ __forceinline__ float eluf(float v){ return v > 0.f ? v : expm1f(v); }

__device__ __forceinline__ void atomicMaxF(float* a, float v){
    if (v >= 0.f) atomicMax((int*)a, __float_as_int(v));
    else          atomicMin((unsigned int*)a, __float_as_uint(v));
}

__device__ __forceinline__ void warpMaxAtomic(float mx, float* dst){
    #pragma unroll
    for (int o = 16; o; o >>= 1) mx = fmaxf(mx, __shfl_xor_sync(0xffffffffu, mx, o));
    if ((threadIdx.x & 31) == 0) atomicMax((int*)dst, __float_as_int(mx)); // nonneg floats
}

__device__ __forceinline__ void spline_corners(float psx, float psy,
                                               int& ix, int& iy, float& fx, float& fy){
    float vx = psx * 4.f, vy = psy * 4.f;
    float fix = fminf(fmaxf(floorf(vx), 0.f), 3.f);
    float fiy = fminf(fmaxf(floorf(vy), 0.f), 3.f);
    fx = vx - fix; fy = vy - fiy;
    ix = (int)fix; iy = (int)fiy;
}

// cluster id for original nodes (pool-1, cell size 4, 8x8)
__device__ __forceinline__ int clu1(int n, const float* __restrict__ pos){
    float px = pos[2*n], py = pos[2*n+1];
    int cx = min(max((int)floorf(px * 0.25f), 0), 7);
    int cy = min(max((int)floorf(py * 0.25f), 0), 7);
    return (n >> 8) * 64 + cx * 8 + cy;   // n/NPG
}
// cluster id for pool-1 nodes (pool-2, cell size 8, 4x4)
__device__ __forceinline__ int clu2(int j){
    float px = d_pos2[2*j], py = d_pos2[2*j+1];
    int cx = min(max((int)floorf(px * 0.125f), 0), 3);
    int cy = min(max((int)floorf(py * 0.125f), 0), 3);
    return (j >> 6) * 16 + cx * 4 + cy;   // j/64
}

// ---------------- init ----------------
__global__ void k_init(){
    long t = (long)blockIdx.x * blockDim.x + threadIdx.x;
    long S = (long)gridDim.x * blockDim.x;
    const float NEG = -3.4e38f;
    float4 z4 = make_float4(0.f,0.f,0.f,0.f);
    float4 n4 = make_float4(NEG,NEG,NEG,NEG);
    for (long i=t;i<NN*KK/4;      i+=S) ((float4*)d_acc1)[i]=z4;
    for (long i=t;i<(long)NC1*KK*F1/4;i+=S) ((float4*)d_acc2)[i]=z4;
    for (long i=t;i<(long)NC2*KK*F2/4;i+=S) ((float4*)d_acc3)[i]=z4;
    for (long i=t;i<NC1*F1/4;     i+=S) ((float4*)d_x2)[i]=n4;
    for (long i=t;i<NC2*F2/4;     i+=S) ((float4*)d_x3)[i]=n4;
    for (long i=t;i<NN;           i+=S) d_deg1[i]=0.f;
    for (long i=t;i<NC1;          i+=S){ d_deg2[i]=0.f; d_cnt1[i]=0.f; }
    for (long i=t;i<NC2;          i+=S){ d_deg3[i]=0.f; d_cnt2[i]=0.f; }
    for (long i=t;i<NC1*2;        i+=S) d_pos2[i]=0.f;
    for (long i=t;i<NC2*2;        i+=S) d_pos3[i]=0.f;
    for (long i=t;i<BM1W;         i+=S) d_bm1[i]=0u;
    for (long i=t;i<BM2W;         i+=S) d_bm2[i]=0u;
    if (t==0){ d_ecnt1[0]=0; d_ecnt2[0]=0; d_m[0]=d_m[1]=d_m[2]=0.f; }
}

// ---------------- layer 1 ----------------
__global__ void k_m1(const float* __restrict__ pos, const int* __restrict__ row,
                     const int* __restrict__ col){
    float mx = 0.f;
    for (int e = blockIdx.x*blockDim.x + threadIdx.x; e < EE; e += gridDim.x*blockDim.x){
        int r = row[e], c = col[e];
        float dx = pos[2*c]   - pos[2*r];
        float dy = pos[2*c+1] - pos[2*r+1];
        mx = fmaxf(mx, fmaxf(fabsf(dx), fabsf(dy)));
    }
    warpMaxAtomic(mx, &d_m[0]);
}

__global__ void k_scatter1(const float* __restrict__ pos, const float* __restrict__ x,
                           const int* __restrict__ row, const int* __restrict__ col){
    int e = blockIdx.x*blockDim.x + threadIdx.x;
    if (e >= EE) return;
    int r = row[e], c = col[e];
    float inv = 1.f / (2.f * d_m[0] + 1e-12f);
    float psx = (pos[2*c]   - pos[2*r])   * inv + 0.5f;
    float psy = (pos[2*c+1] - pos[2*r+1]) * inv + 0.5f;
    int ix, iy; float fx, fy;
    spline_corners(psx, psy, ix, iy, fx, fy);
    float xin = x[c];
    float wxs[2] = {1.f-fx, fx}, wys[2] = {1.f-fy, fy};
    #pragma unroll
    for (int sx=0; sx<2; sx++)
        #pragma unroll
        for (int sy=0; sy<2; sy++)
            atomicAdd(&d_acc1[r*KK + (ix+sx)*5 + (iy+sy)], wxs[sx]*wys[sy]*xin);
    atomicAdd(&d_deg1[r], 1.f);
}

__global__ void k_node1(const float* __restrict__ x, const float* __restrict__ W1,
                        const float* __restrict__ r1, const float* __restrict__ b1){
    __shared__ float sW[KK*F1], sr[F1], sb[F1];
    for (int i = threadIdx.x; i < KK*F1; i += blockDim.x) sW[i] = W1[i];
    if (threadIdx.x < F1){ sr[threadIdx.x] = r1[threadIdx.x]; sb[threadIdx.x] = b1[threadIdx.x]; }
    __syncthreads();
    int n = blockIdx.x * 8 + (threadIdx.x >> 5);
    int o = threadIdx.x & 31;
    if (n >= NN) return;
    float s = 0.f;
    #pragma unroll
    for (int k = 0; k < KK; k++) s += d_acc1[n*KK + k] * sW[k*F1 + o];
    float dg = fmaxf(d_deg1[n], 1.f);
    float v = s / dg + x[n] * sr[o] + sb[o];
    d_h1[n*F1 + o] = eluf(v);
}

// ---------------- pool 1 ----------------
__global__ void k_pool1(const float* __restrict__ pos){
    int w = (blockIdx.x*blockDim.x + threadIdx.x) >> 5;
    int lane = threadIdx.x & 31;
    if (w >= NN) return;
    float px = pos[2*w], py = pos[2*w+1];
    int cx = min(max((int)floorf(px*0.25f),0),7);
    int cy = min(max((int)floorf(py*0.25f),0),7);
    int cl = (w >> 8) * 64 + cx*8 + cy;
    atomicMaxF(&d_x2[cl*F1 + lane], d_h1[w*F1 + lane]);
    if (lane == 0){
        atomicAdd(&d_cnt1[cl], 1.f);
        atomicAdd(&d_pos2[2*cl],   px);
        atomicAdd(&d_pos2[2*cl+1], py);
    }
}

__global__ void k_fin1(){
    int t = blockIdx.x*blockDim.x + threadIdx.x;
    if (t >= NC1*F1) return;
    int cl = t / F1, f = t % F1;
    float cnt = d_cnt1[cl];
    if (f < 2) d_pos2[2*cl + f] *= 1.f / fmaxf(cnt, 1.f);
    if (cnt <= 0.f) d_x2[t] = 0.f;
}

__global__ void k_remap1(const float* __restrict__ pos, const int* __restrict__ row,
                         const int* __restrict__ col){
    int e = blockIdx.x*blockDim.x + threadIdx.x;
    if (e >= EE) return;
    int r2 = clu1(row[e], pos);
    int c2 = clu1(col[e], pos);
    if (r2 == c2) return;
    int gg = r2 >> 6;
    int key = (gg << 12) | ((r2 & 63) << 6) | (c2 & 63);
    unsigned bit = 1u << (key & 31);
    unsigned old = atomicOr(&d_bm1[key >> 5], bit);
    if (!(old & bit)){
        int i = atomicAdd(&d_ecnt1[0], 1);
        d_er2[i] = r2; d_ec2[i] = c2;
    }
}

// ---------------- layer 2 ----------------
__global__ void k_m2(){
    int nE = d_ecnt1[0];
    float mx = 0.f;
    for (int e = blockIdx.x*blockDim.x + threadIdx.x; e < nE; e += gridDim.x*blockDim.x){
        int r = d_er2[e], c = d_ec2[e];
        float dx = d_pos2[2*c]   - d_pos2[2*r];
        float dy = d_pos2[2*c+1] - d_pos2[2*r+1];
        mx = fmaxf(mx, fmaxf(fabsf(dx), fabsf(dy)));
    }
    warpMaxAtomic(mx, &d_m[1]);
}

__global__ void k_scatter2(){
    int lane = threadIdx.x & 31;
    int warp = (blockIdx.x*blockDim.x + threadIdx.x) >> 5;
    int nW   = (gridDim.x*blockDim.x) >> 5;
    int nE = d_ecnt1[0];
    float inv = 1.f / (2.f * d_m[1] + 1e-12f);
    for (int e = warp; e < nE; e += nW){
        int r = d_er2[e], c = d_ec2[e];
        float psx = (d_pos2[2*c]   - d_pos2[2*r])   * inv + 0.5f;
        float psy = (d_pos2[2*c+1] - d_pos2[2*r+1]) * inv + 0.5f;
        int ix, iy; float fx, fy;
        spline_corners(psx, psy, ix, iy, fx, fy);
        float xin = d_x2[c*F1 + lane];
        float wxs[2] = {1.f-fx, fx}, wys[2] = {1.f-fy, fy};
        #pragma unroll
        for (int sx=0; sx<2; sx++)
            #pragma unroll
            for (int sy=0; sy<2; sy++){
                int idx = (ix+sx)*5 + (iy+sy);
                atomicAdd(&d_acc2[(r*KK + idx)*F1 + lane], wxs[sx]*wys[sy]*xin);
            }
        if (lane == 0) atomicAdd(&d_deg2[r], 1.f);
    }
}

// ---------------- fused GEMM + root + bias + ELU ----------------
template<int KDIM, int FIN, int NOUT>
__device__ __forceinline__ void gemm_body(
    const float* __restrict__ A, const float* __restrict__ W,
    const float* __restrict__ XIN, const float* __restrict__ ROOT,
    const float* __restrict__ BIAS, const float* __restrict__ DEG,
    float* __restrict__ OUT)
{
    const int BM = 64, BN = 64, BK = 16;
    __shared__ float As[BK][BM + 4];   // row stride 68 floats (16B aligned rows)
    __shared__ float Bs[BK][BN];
    int bm = blockIdx.x * BM;
    int bn = blockIdx.y * BN;
    int t  = threadIdx.x;              // 256
    int tx = t & 15, ty = t >> 4;
    float acc[4][4] = {};
    for (int kk = 0; kk < KDIM; kk += BK){
        #pragma unroll
        for (int r = 0; r < 4; r++){
            int idx = t + r*256;
            int m = idx >> 4, k = idx & 15;
            As[k][m] = A[(long)(bm + m)*KDIM + kk + k];
        }
        #pragma unroll
        for (int r = 0; r < 4; r++){
            int idx = t + r*256;
            int k = idx >> 6, n = idx & 63;
            Bs[k][n] = W[(kk + k)*NOUT + bn + n];
        }
        __syncthreads();
        #pragma unroll
        for (int kb = 0; kb < BK; kb++){
            float4 a = *(const float4*)&As[kb][ty*4];
            float4 b = *(const float4*)&Bs[kb][tx*4];
            float av[4] = {a.x,a.y,a.z,a.w};
            float bv[4] = {b.x,b.y,b.z,b.w};
            #pragma unroll
            for (int i2=0;i2<4;i2++)
                #pragma unroll
                for (int j=0;j<4;j++) acc[i2][j] += av[i2]*bv[j];
        }
        __syncthreads();
    }
    #pragma unroll
    for (int i2 = 0; i2 < 4; i2++){
        int m = bm + ty*4 + i2;
        float inv = 1.f / fmaxf(DEG[m], 1.f);
        #pragma unroll
        for (int j = 0; j < 4; j++){
            int o = bn + tx*4 + j;
            float rsum = 0.f;
            for (int i = 0; i < FIN; i++) rsum += XIN[m*FIN + i] * ROOT[i*NOUT + o];
            float v = acc[i2][j]*inv + rsum + BIAS[o];
            OUT[m*NOUT + o] = eluf(v);
        }
    }
}

__global__ void k_gemm2(const float* __restrict__ W, const float* __restrict__ ROOT,
                        const float* __restrict__ BIAS){
    gemm_body<KK*F1, F1, F2>(d_acc2, W, d_x2, ROOT, BIAS, d_deg2, d_h2);
}
__global__ void k_gemm3(const float* __restrict__ W, const float* __restrict__ ROOT,
                        const float* __restrict__ BIAS){
    gemm_body<KK*F2, F2, F3>(d_acc3, W, d_x3, ROOT, BIAS, d_deg3, d_h3);
}

// ---------------- pool 2 ----------------
__global__ void k_pool2(){
    int w = (blockIdx.x*blockDim.x + threadIdx.x) >> 5;
    int lane = threadIdx.x & 31;
    if (w >= NC1) return;
    if (d_cnt1[w] <= 0.f) return;     // empty pool-1 cluster: excluded
    float px = d_pos2[2*w], py = d_pos2[2*w+1];
    int cx = min(max((int)floorf(px*0.125f),0),3);
    int cy = min(max((int)floorf(py*0.125f),0),3);
    int cl = (w >> 6) * 16 + cx*4 + cy;
    atomicMaxF(&d_x3[cl*F2 + lane],      d_h2[w*F2 + lane]);
    atomicMaxF(&d_x3[cl*F2 + lane + 32], d_h2[w*F2 + lane + 32]);
    if (lane == 0){
        atomicAdd(&d_cnt2[cl], 1.f);
        atomicAdd(&d_pos3[2*cl],   px);
        atomicAdd(&d_pos3[2*cl+1], py);
    }
}

__global__ void k_fin2(){
    int t = blockIdx.x*blockDim.x + threadIdx.x;
    if (t >= NC2*F2) return;
    int cl = t / F2, f = t % F2;
    float cnt = d_cnt2[cl];
    if (f < 2) d_pos3[2*cl + f] *= 1.f / fmaxf(cnt, 1.f);
    if (cnt <= 0.f) d_x3[t] = 0.f;
}

__global__ void k_remap2(){
    int nE = d_ecnt1[0];
    for (int e = blockIdx.x*blockDim.x + threadIdx.x; e < nE; e += gridDim.x*blockDim.x){
        int r3 = clu2(d_er2[e]);
        int c3 = clu2(d_ec2[e]);
        if (r3 == c3) continue;
        int gg = r3 >> 4;
        int key = (gg << 8) | ((r3 & 15) << 4) | (c3 & 15);
        unsigned bit = 1u << (key & 31);
        unsigned old = atomicOr(&d_bm2[key >> 5], bit);
        if (!(old & bit)){
            int i = atomicAdd(&d_ecnt2[0], 1);
            d_er3[i] = r3; d_ec3[i] = c3;
        }
    }
}

// ---------------- layer 3 ----------------
__global__ void k_m3(){
    int nE = d_ecnt2[0];
    float mx = 0.f;
    for (int e = blockIdx.x*blockDim.x + threadIdx.x; e < nE; e += gridDim.x*blockDim.x){
        int r = d_er3[e], c = d_ec3[e];
        float dx = d_pos3[2*c]   - d_pos3[2*r];
        float dy = d_pos3[2*c+1] - d_pos3[2*r+1];
        mx = fmaxf(mx, fmaxf(fabsf(dx), fabsf(dy)));
    }
    warpMaxAtomic(mx, &d_m[2]);
}

__global__ void k_scatter3(){
    int lane = threadIdx.x & 31;
    int warp = (blockIdx.x*blockDim.x + threadIdx.x) >> 5;
    int nW   = (gridDim.x*blockDim.x) >> 5;
    int nE = d_ecnt2[0];
    float inv = 1.f / (2.f * d_m[2] + 1e-12f);
    for (int e = warp; e < nE; e += nW){
        int r = d_er3[e], c = d_ec3[e];
        float psx = (d_pos3[2*c]   - d_pos3[2*r])   * inv + 0.5f;
        float psy = (d_pos3[2*c+1] - d_pos3[2*r+1]) * inv + 0.5f;
        int ix, iy; float fx, fy;
        spline_corners(psx, psy, ix, iy, fx, fy);
        float x0 = d_x3[c*F2 + lane];
        float x1 = d_x3[c*F2 + lane + 32];
        float wxs[2] = {1.f-fx, fx}, wys[2] = {1.f-fy, fy};
        #pragma unroll
        for (int sx=0; sx<2; sx++)
            #pragma unroll
            for (int sy=0; sy<2; sy++){
                int idx = (ix+sx)*5 + (iy+sy);
                float b = wxs[sx]*wys[sy];
                atomicAdd(&d_acc3[(r*KK + idx)*F2 + lane],      b*x0);
                atomicAdd(&d_acc3[(r*KK + idx)*F2 + lane + 32], b*x1);
            }
        if (lane == 0) atomicAdd(&d_deg3[r], 1.f);
    }
}

// ---------------- readout ----------------
__global__ void k_readout(const float* __restrict__ fcw, const float* __restrict__ fcb,
                          float* __restrict__ out){
    int g = blockIdx.x, t = threadIdx.x;     // 128 threads
    __shared__ float sf[F3];
    __shared__ float slg[10];
    float s = 0.f, cnt = 0.f;
    for (int j = 0; j < 16; j++){
        int n = g*16 + j;
        float nv = d_cnt2[n] > 0.f ? 1.f : 0.f;
        cnt += nv;
        s += nv * d_h3[n*F3 + t];
    }
    sf[t] = s / fmaxf(cnt, 1.f);
    __syncthreads();
    if (t < 10){
        float l = fcb[t];
        for (int i = 0; i < F3; i++) l += sf[i] * fcw[i*10 + t];
        slg[t] = l;
    }
    __syncthreads();
    if (t == 0){
        float mx = slg[0];
        for (int o = 1; o < 10; o++) mx = fmaxf(mx, slg[o]);
        float se = 0.f;
        for (int o = 0; o < 10; o++) se += expf(slg[o] - mx);
        float lse = logf(se) + mx;
        for (int o = 0; o < 10; o++) out[g*10 + o] = slg[o] - lse;
    }
}

// ---------------- launch ----------------
extern "C" void kernel_launch(void* const* d_in, const int* in_sizes, int n_in,
                              void* d_out, int out_size){
    const float* x    = (const float*)d_in[0];
    const float* pos  = (const float*)d_in[1];
    const int*   ei   = (const int*)  d_in[2];
    const float* W1   = (const float*)d_in[4];
    const float* r1   = (const float*)d_in[5];
    const float* b1   = (const float*)d_in[6];
    const float* W2   = (const float*)d_in[7];
    const float* r2p  = (const float*)d_in[8];
    const float* b2   = (const float*)d_in[9];
    const float* W3   = (const float*)d_in[10];
    const float* r3p  = (const float*)d_in[11];
    const float* b3   = (const float*)d_in[12];
    const float* fcw  = (const float*)d_in[13];
    const float* fcb  = (const float*)d_in[14];
    float* out = (float*)d_out;
    const int* row = ei;        // edge_index[0] = targets
    const int* col = ei + EE;   // edge_index[1] = sources

    k_init    <<<2048, 256>>>();
    k_m1      <<<1024, 256>>>(pos, row, col);
    k_scatter1<<<EE/256, 256>>>(pos, x, row, col);
    k_node1   <<<NN/8, 256>>>(x, W1, r1, b1);
    k_pool1   <<<NN/8, 256>>>(pos);
    k_fin1    <<<NC1*F1/256, 256>>>();
    k_remap1  <<<EE/256, 256>>>(pos, row, col);
    k_m2      <<<512, 256>>>();
    k_scatter2<<<2048, 256>>>();
    k_gemm2   <<<dim3(NC1/64, 1), 256>>>(W2, r2p, b2);
    k_pool2   <<<NC1/8, 256>>>();
    k_fin2    <<<NC2*F2/256, 256>>>();
    k_remap2  <<<1024, 256>>>();
    k_m3      <<<256, 256>>>();
    k_scatter3<<<512, 256>>>();
    k_gemm3   <<<dim3(NC2/64, F3/64), 256>>>(W3, r3p, b3);
    k_readout <<<BG, 128>>>(fcw, fcb, out);
}

// round 4
// speedup vs baseline: 1.0050x; 1.0050x over previous
#include <cuda_runtime.h>
#include <math.h>

// ---------------- problem constants ----------------
#define BG   256
#define NPG  256
#define NN   (BG*NPG)            // 65536 nodes
#define EE   (NN*16)             // 1048576 edges
#define KK   25
#define F1   32
#define F2   64
#define F3   128
#define NC1  (BG*64)             // 16384 pool-1 clusters
#define NC2  (BG*16)             // 4096  pool-2 clusters
#define BM1W (BG*4096/32)
#define BM2W (BG*256/32)
#define E3CAP 65536
#define B2SZ (BG*KK*64*64)       // 26,214,400 floats
#define B3SZ (BG*KK*16*16)       // 1,638,400 floats

// ---------------- device scratch ----------------
__device__ float    d_m[4];
__device__ int      d_ecnt1[1];
__device__ int      d_ecnt2[1];
__device__ float    d_acc1[NN*32];          // padded stride 32 (25 basis + slot25 = degree)
__device__ float    d_h1[NN*F1];
__device__ float    d_x2[NC1*F1];
__device__ float    d_cnt1[NC1];
__device__ float    d_pos2[NC1*2];
__device__ int      d_er2[EE];
__device__ int      d_ec2[EE];
__device__ unsigned d_bm1[BM1W];
__device__ float    d_B2[B2SZ];
__device__ float    d_acc2[NC1*KK*F1];
__device__ float    d_deg2[NC1];
__device__ float    d_h2[NC1*F2];
__device__ float    d_x3[NC2*F2];
__device__ float    d_cnt2[NC2];
__device__ float    d_pos3[NC2*2];
__device__ int      d_er3[E3CAP];
__device__ int      d_ec3[E3CAP];
__device__ unsigned d_bm2[BM2W];
__device__ float    d_B3[B3SZ];
__device__ float    d_acc3[NC2*KK*F2];
__device__ float    d_deg3[NC2];
__device__ float    d_h3[NC2*F3];

// ---------------- helpers ----------------
__device__ __forceinline__ float eluf(float v){ return v > 0.f ? v : expm1f(v); }

__device__ __forceinline__ void atomicMaxF(float* a, float v){
    if (v >= 0.f) atomicMax((int*)a, __float_as_int(v));
    else          atomicMin((unsigned int*)a, __float_as_uint(v));
}

__device__ __forceinline__ void warpMaxAtomic(float mx, float* dst){
    #pragma unroll
    for (int o = 16; o; o >>= 1) mx = fmaxf(mx, __shfl_xor_sync(0xffffffffu, mx, o));
    if ((threadIdx.x & 31) == 0) atomicMax((int*)dst, __float_as_int(mx));
}

__device__ __forceinline__ void spline_corners(float psx, float psy,
                                               int& ix, int& iy, float& fx, float& fy){
    float vx = psx * 4.f, vy = psy * 4.f;
    float fix = fminf(fmaxf(floorf(vx), 0.f), 3.f);
    float fiy = fminf(fmaxf(floorf(vy), 0.f), 3.f);
    fx = vx - fix; fy = vy - fiy;
    ix = (int)fix; iy = (int)fiy;
}

__device__ __forceinline__ int clu1(int n, const float* __restrict__ pos){
    float px = pos[2*n], py = pos[2*n+1];
    int cx = min(max((int)floorf(px * 0.25f), 0), 7);
    int cy = min(max((int)floorf(py * 0.25f), 0), 7);
    return (n >> 8) * 64 + cx * 8 + cy;
}
__device__ __forceinline__ int clu2(int j){
    float px = d_pos2[2*j], py = d_pos2[2*j+1];
    int cx = min(max((int)floorf(px * 0.125f), 0), 3);
    int cy = min(max((int)floorf(py * 0.125f), 0), 3);
    return (j >> 6) * 16 + cx * 4 + cy;
}

// f32x2 packed FMA helpers
__device__ __forceinline__ unsigned long long splat2(float x){
    unsigned long long r;
    asm("mov.b64 %0, {%1, %1};" : "=l"(r) : "f"(x));
    return r;
}
__device__ __forceinline__ void ffma2(unsigned long long& d,
                                      unsigned long long a, unsigned long long b){
    asm("fma.rn.f32x2 %0, %1, %2, %0;" : "+l"(d) : "l"(a), "l"(b));
}
__device__ __forceinline__ float f2lo(unsigned long long u){ return __uint_as_float((unsigned)u); }
__device__ __forceinline__ float f2hi(unsigned long long u){ return __uint_as_float((unsigned)(u>>32)); }

// ---------------- init ----------------
__global__ void k_init(){
    long t = (long)blockIdx.x * blockDim.x + threadIdx.x;
    long S = (long)gridDim.x * blockDim.x;
    const float NEG = -3.4e38f;
    float4 z4 = make_float4(0.f,0.f,0.f,0.f);
    float4 n4 = make_float4(NEG,NEG,NEG,NEG);
    for (long i=t;i<B2SZ/4;       i+=S) ((float4*)d_B2)[i]=z4;
    for (long i=t;i<B3SZ/4;       i+=S) ((float4*)d_B3)[i]=z4;
    for (long i=t;i<(long)NN*32/4;i+=S) ((float4*)d_acc1)[i]=z4;
    for (long i=t;i<NC1*F1/4;     i+=S) ((float4*)d_x2)[i]=n4;
    for (long i=t;i<NC2*F2/4;     i+=S) ((float4*)d_x3)[i]=n4;
    for (long i=t;i<NC1;          i+=S){ d_deg2[i]=0.f; d_cnt1[i]=0.f; }
    for (long i=t;i<NC2;          i+=S){ d_deg3[i]=0.f; d_cnt2[i]=0.f; }
    for (long i=t;i<NC1*2;        i+=S) d_pos2[i]=0.f;
    for (long i=t;i<NC2*2;        i+=S) d_pos3[i]=0.f;
    for (long i=t;i<BM1W;         i+=S) d_bm1[i]=0u;
    for (long i=t;i<BM2W;         i+=S) d_bm2[i]=0u;
    if (t==0){ d_ecnt1[0]=0; d_ecnt2[0]=0; d_m[0]=d_m[1]=d_m[2]=0.f; }
}

// ---------------- layer 1 ----------------
__global__ void k_m1(const float* __restrict__ pos, const int* __restrict__ row,
                     const int* __restrict__ col){
    float mx = 0.f;
    for (int e = blockIdx.x*blockDim.x + threadIdx.x; e < EE; e += gridDim.x*blockDim.x){
        int r = row[e], c = col[e];
        float dx = pos[2*c]   - pos[2*r];
        float dy = pos[2*c+1] - pos[2*r+1];
        mx = fmaxf(mx, fmaxf(fabsf(dx), fabsf(dy)));
    }
    warpMaxAtomic(mx, &d_m[0]);
}

__global__ void k_scatter1(const float* __restrict__ pos, const float* __restrict__ x,
                           const int* __restrict__ row, const int* __restrict__ col){
    int e = blockIdx.x*blockDim.x + threadIdx.x;
    if (e >= EE) return;
    int r = row[e], c = col[e];
    float inv = 1.f / (2.f * d_m[0] + 1e-12f);
    float psx = (pos[2*c]   - pos[2*r])   * inv + 0.5f;
    float psy = (pos[2*c+1] - pos[2*r+1]) * inv + 0.5f;
    int ix, iy; float fx, fy;
    spline_corners(psx, psy, ix, iy, fx, fy);
    float xin = x[c];
    float wxs[2] = {1.f-fx, fx}, wys[2] = {1.f-fy, fy};
    #pragma unroll
    for (int sx=0; sx<2; sx++)
        #pragma unroll
        for (int sy=0; sy<2; sy++)
            atomicAdd(&d_acc1[r*32 + (ix+sx)*5 + (iy+sy)], wxs[sx]*wys[sy]*xin);
    atomicAdd(&d_acc1[r*32 + 25], 1.f);    // true degree, same cache line
}

__global__ void k_node1(const float* __restrict__ x, const float* __restrict__ W1,
                        const float* __restrict__ r1, const float* __restrict__ b1){
    __shared__ float sW[KK*F1], sr[F1], sb[F1];
    for (int i = threadIdx.x; i < KK*F1; i += blockDim.x) sW[i] = W1[i];
    if (threadIdx.x < F1){ sr[threadIdx.x] = r1[threadIdx.x]; sb[threadIdx.x] = b1[threadIdx.x]; }
    __syncthreads();
    int n = blockIdx.x * 8 + (threadIdx.x >> 5);
    int o = threadIdx.x & 31;
    float s = 0.f;
    #pragma unroll
    for (int k4 = 0; k4 < 24; k4 += 4){
        float4 a = *(const float4*)&d_acc1[n*32 + k4];
        s += a.x * sW[(k4+0)*F1 + o];
        s += a.y * sW[(k4+1)*F1 + o];
        s += a.z * sW[(k4+2)*F1 + o];
        s += a.w * sW[(k4+3)*F1 + o];
    }
    s += d_acc1[n*32 + 24] * sW[24*F1 + o];
    float dg = fmaxf(d_acc1[n*32 + 25], 1.f);   // degree from slot 25
    float v = s / dg + x[n] * sr[o] + sb[o];
    d_h1[n*F1 + o] = eluf(v);
}

// ---------------- pool 1 ----------------
__global__ void k_pool1(const float* __restrict__ pos){
    int w = (blockIdx.x*blockDim.x + threadIdx.x) >> 5;
    int lane = threadIdx.x & 31;
    if (w >= NN) return;
    float px = pos[2*w], py = pos[2*w+1];
    int cx = min(max((int)floorf(px*0.25f),0),7);
    int cy = min(max((int)floorf(py*0.25f),0),7);
    int cl = (w >> 8) * 64 + cx*8 + cy;
    atomicMaxF(&d_x2[cl*F1 + lane], d_h1[w*F1 + lane]);
    if (lane == 0){
        atomicAdd(&d_cnt1[cl], 1.f);
        atomicAdd(&d_pos2[2*cl],   px);
        atomicAdd(&d_pos2[2*cl+1], py);
    }
}

__global__ void k_fin1(){
    int t = blockIdx.x*blockDim.x + threadIdx.x;
    if (t >= NC1*F1) return;
    int cl = t / F1, f = t % F1;
    float cnt = d_cnt1[cl];
    if (f < 2) d_pos2[2*cl + f] *= 1.f / fmaxf(cnt, 1.f);
    if (cnt <= 0.f) d_x2[t] = 0.f;
}

// ---------------- build unique level-2 edge list (warp-aggregated append) ----------------
__global__ void k_remap1(const float* __restrict__ pos, const int* __restrict__ row,
                         const int* __restrict__ col){
    int e = blockIdx.x*blockDim.x + threadIdx.x;
    bool newe = false; int r2 = 0, c2 = 0;
    if (e < EE){
        r2 = clu1(row[e], pos);
        c2 = clu1(col[e], pos);
        if (r2 != c2){
            int key = ((r2 >> 6) << 12) | ((r2 & 63) << 6) | (c2 & 63);
            unsigned bit = 1u << (key & 31);
            unsigned old = atomicOr(&d_bm1[key >> 5], bit);
            newe = !(old & bit);
        }
    }
    unsigned mball = __ballot_sync(0xffffffffu, newe);
    if (!mball) return;
    int lane = threadIdx.x & 31;
    int leader = __ffs(mball) - 1;
    int base = 0;
    if (lane == leader) base = atomicAdd(&d_ecnt1[0], __popc(mball));
    base = __shfl_sync(0xffffffffu, base, leader);
    if (newe){
        int ofs = __popc(mball & ((1u << lane) - 1u));
        d_er2[base + ofs] = r2;
        d_ec2[base + ofs] = c2;
    }
}

__global__ void k_m2(){
    int nE = d_ecnt1[0];
    float mx = 0.f;
    for (int e = blockIdx.x*blockDim.x + threadIdx.x; e < nE; e += gridDim.x*blockDim.x){
        int r = d_er2[e], c = d_ec2[e];
        float dx = d_pos2[2*c]   - d_pos2[2*r];
        float dy = d_pos2[2*c+1] - d_pos2[2*r+1];
        mx = fmaxf(mx, fmaxf(fabsf(dx), fabsf(dy)));
    }
    warpMaxAtomic(mx, &d_m[1]);
}

// fill dense basis B2[g][k][r][c] + deg2 (plain stores, unique edges)
__global__ void k_fillB2(){
    int nE = d_ecnt1[0];
    float inv = 1.f / (2.f * d_m[1] + 1e-12f);
    for (int e = blockIdx.x*blockDim.x + threadIdx.x; e < nE; e += gridDim.x*blockDim.x){
        int r = d_er2[e], c = d_ec2[e];
        int g = r >> 6;
        float psx = (d_pos2[2*c]   - d_pos2[2*r])   * inv + 0.5f;
        float psy = (d_pos2[2*c+1] - d_pos2[2*r+1]) * inv + 0.5f;
        int ix, iy; float fx, fy;
        spline_corners(psx, psy, ix, iy, fx, fy);
        float wxs[2] = {1.f-fx, fx}, wys[2] = {1.f-fy, fy};
        int rl = r & 63, cl = c & 63;
        #pragma unroll
        for (int sx=0; sx<2; sx++)
            #pragma unroll
            for (int sy=0; sy<2; sy++){
                int idx = (ix+sx)*5 + (iy+sy);
                d_B2[(((long)(g*KK + idx))*64 + rl)*64 + cl] = wxs[sx]*wys[sy];
            }
        atomicAdd(&d_deg2[r], 1.f);
    }
}

// acc2[g,r,k,i] = sum_c B2[g,k,r,c] * x2[g,c,i]   — one block per (g,k)
__global__ void k_bgemm2(){
    __shared__ float Bt[64][66];     // [c][r]; row = 264B (8B-aligned for u64 LDS)
    __shared__ float xs[64][32];     // [c][i]
    int g = blockIdx.x / KK;
    int k = blockIdx.x % KK;
    size_t bbase = (size_t)blockIdx.x * 4096;
    int t = threadIdx.x;
    // load B tile transposed
    #pragma unroll
    for (int w = 0; w < 4; w++){
        int idx = t + w*256;            // float4 index, 1024 total
        int r = idx >> 4, c4 = (idx & 15) * 4;
        float4 v = *(const float4*)&d_B2[bbase + r*64 + c4];
        Bt[c4+0][r]=v.x; Bt[c4+1][r]=v.y; Bt[c4+2][r]=v.z; Bt[c4+3][r]=v.w;
    }
    // load x2 tile
    #pragma unroll
    for (int w = 0; w < 2; w++){
        int idx = t + w*256;            // float4 index, 512 total
        int c = idx >> 3, i4 = (idx & 7) * 4;
        *(float4*)&xs[c][i4] = *(const float4*)&d_x2[(g*64 + c)*F1 + i4];
    }
    __syncthreads();
    int tx = t & 7;          // i-group
    int ty = t >> 3;         // r-pair 0..31
    unsigned long long acc[4] = {0ull,0ull,0ull,0ull};
    #pragma unroll 8
    for (int c = 0; c < 64; c++){
        unsigned long long a = *(const unsigned long long*)&Bt[c][ty*2];
        float4 xv = *(const float4*)&xs[c][tx*4];
        ffma2(acc[0], a, splat2(xv.x));
        ffma2(acc[1], a, splat2(xv.y));
        ffma2(acc[2], a, splat2(xv.z));
        ffma2(acc[3], a, splat2(xv.w));
    }
    int r0 = ty*2;
    float4 o0 = make_float4(f2lo(acc[0]), f2lo(acc[1]), f2lo(acc[2]), f2lo(acc[3]));
    float4 o1 = make_float4(f2hi(acc[0]), f2hi(acc[1]), f2hi(acc[2]), f2hi(acc[3]));
    *(float4*)&d_acc2[((long)(g*64 + r0  ))*(KK*F1) + k*F1 + tx*4] = o0;
    *(float4*)&d_acc2[((long)(g*64 + r0+1))*(KK*F1) + k*F1 + tx*4] = o1;
}

// ---------------- fused GEMM (+root as K-extension) + deg + bias + ELU ----------------
template<int BM, int TMH, int KDIM, int FIN, int NOUT>
__device__ __forceinline__ void gemm_body(
    const float* __restrict__ A, const float* __restrict__ W,
    const float* __restrict__ XIN, const float* __restrict__ ROOT,
    const float* __restrict__ BIAS, const float* __restrict__ DEG,
    float* __restrict__ OUT)
{
    const int BK = 16, BN = 64, TM = 2*TMH;
    __shared__ float As[BK][BM + 4];
    __shared__ float Bs[BK][BN];
    int bm = blockIdx.x * BM;
    int bn = blockIdx.y * BN;
    int t  = threadIdx.x;            // 256
    int tx = t & 15, ty = t >> 4;
    unsigned long long accA[TMH][4];
    unsigned long long accR[TMH][4];
    #pragma unroll
    for (int p=0;p<TMH;p++)
        #pragma unroll
        for (int j=0;j<4;j++){ accA[p][j]=0ull; accR[p][j]=0ull; }

    const int KTOT = KDIM + FIN;
    for (int kk = 0; kk < KTOT; kk += BK){
        bool ext = (kk >= KDIM);
        const float* srcA = ext ? XIN : A;
        const float* srcB = ext ? ROOT : W;
        int ld   = ext ? FIN : KDIM;
        int kofs = ext ? (kk - KDIM) : kk;
        #pragma unroll
        for (int w = 0; w < BM*BK/1024; w++){
            int idx = (t + w*256) * 4;
            int m = idx >> 4, k4 = idx & 15;
            float4 v = *(const float4*)&srcA[(long)(bm+m)*ld + kofs + k4];
            As[k4+0][m]=v.x; As[k4+1][m]=v.y; As[k4+2][m]=v.z; As[k4+3][m]=v.w;
        }
        {
            int k = t >> 4, n4 = (t & 15) * 4;
            *(float4*)&Bs[k][n4] = *(const float4*)&srcB[(long)(kofs+k)*NOUT + bn + n4];
        }
        __syncthreads();
        if (!ext){
            #pragma unroll
            for (int kb = 0; kb < BK; kb++){
                unsigned long long a[TMH];
                #pragma unroll
                for (int p=0;p<TMH;p++)
                    a[p] = *(const unsigned long long*)&As[kb][ty*TM + 2*p];
                float4 b4 = *(const float4*)&Bs[kb][tx*4];
                unsigned long long b0=splat2(b4.x), b1=splat2(b4.y),
                                   b2=splat2(b4.z), b3=splat2(b4.w);
                #pragma unroll
                for (int p=0;p<TMH;p++){
                    ffma2(accA[p][0], a[p], b0);
                    ffma2(accA[p][1], a[p], b1);
                    ffma2(accA[p][2], a[p], b2);
                    ffma2(accA[p][3], a[p], b3);
                }
            }
        } else {
            #pragma unroll
            for (int kb = 0; kb < BK; kb++){
                unsigned long long a[TMH];
                #pragma unroll
                for (int p=0;p<TMH;p++)
                    a[p] = *(const unsigned long long*)&As[kb][ty*TM + 2*p];
                float4 b4 = *(const float4*)&Bs[kb][tx*4];
                unsigned long long b0=splat2(b4.x), b1=splat2(b4.y),
                                   b2=splat2(b4.z), b3=splat2(b4.w);
                #pragma unroll
                for (int p=0;p<TMH;p++){
                    ffma2(accR[p][0], a[p], b0);
                    ffma2(accR[p][1], a[p], b1);
                    ffma2(accR[p][2], a[p], b2);
                    ffma2(accR[p][3], a[p], b3);
                }
            }
        }
        __syncthreads();
    }
    #pragma unroll
    for (int p = 0; p < TMH; p++){
        int m0 = bm + ty*TM + 2*p;
        float inv0 = 1.f / fmaxf(DEG[m0],   1.f);
        float inv1 = 1.f / fmaxf(DEG[m0+1], 1.f);
        #pragma unroll
        for (int j = 0; j < 4; j++){
            int o = bn + tx*4 + j;
            float bia = BIAS[o];
            OUT[(long)m0*NOUT + o]     = eluf(f2lo(accA[p][j])*inv0 + f2lo(accR[p][j]) + bia);
            OUT[(long)(m0+1)*NOUT + o] = eluf(f2hi(accA[p][j])*inv1 + f2hi(accR[p][j]) + bia);
        }
    }
}

__global__ void k_gemm2(const float* __restrict__ W, const float* __restrict__ ROOT,
                        const float* __restrict__ BIAS){
    gemm_body<128, 4, KK*F1, F1, F2>(d_acc2, W, d_x2, ROOT, BIAS, d_deg2, d_h2);
}
__global__ void k_gemm3(const float* __restrict__ W, const float* __restrict__ ROOT,
                        const float* __restrict__ BIAS){
    gemm_body<64, 2, KK*F2, F2, F3>(d_acc3, W, d_x3, ROOT, BIAS, d_deg3, d_h3);
}

// ---------------- pool 2 ----------------
__global__ void k_pool2(){
    int w = (blockIdx.x*blockDim.x + threadIdx.x) >> 5;
    int lane = threadIdx.x & 31;
    if (w >= NC1) return;
    if (d_cnt1[w] <= 0.f) return;
    float px = d_pos2[2*w], py = d_pos2[2*w+1];
    int cx = min(max((int)floorf(px*0.125f),0),3);
    int cy = min(max((int)floorf(py*0.125f),0),3);
    int cl = (w >> 6) * 16 + cx*4 + cy;
    atomicMaxF(&d_x3[cl*F2 + lane],      d_h2[w*F2 + lane]);
    atomicMaxF(&d_x3[cl*F2 + lane + 32], d_h2[w*F2 + lane + 32]);
    if (lane == 0){
        atomicAdd(&d_cnt2[cl], 1.f);
        atomicAdd(&d_pos3[2*cl],   px);
        atomicAdd(&d_pos3[2*cl+1], py);
    }
}

__global__ void k_fin2(){
    int t = blockIdx.x*blockDim.x + threadIdx.x;
    if (t >= NC2*F2) return;
    int cl = t / F2, f = t % F2;
    float cnt = d_cnt2[cl];
    if (f < 2) d_pos3[2*cl + f] *= 1.f / fmaxf(cnt, 1.f);
    if (cnt <= 0.f) d_x3[t] = 0.f;
}

// ---------------- build unique level-3 edges ----------------
__global__ void k_remap2(){
    int nE = d_ecnt1[0];
    int lane = threadIdx.x & 31;
    int gw   = (blockIdx.x*blockDim.x + threadIdx.x) >> 5;
    int nW   = (gridDim.x*blockDim.x) >> 5;
    for (int b = gw*32; b < nE; b += nW*32){
        int e = b + lane;
        bool newe = false; int r3 = 0, c3 = 0;
        if (e < nE){
            r3 = clu2(d_er2[e]);
            c3 = clu2(d_ec2[e]);
            if (r3 != c3){
                int key = ((r3 >> 4) << 8) | ((r3 & 15) << 4) | (c3 & 15);
                unsigned bit = 1u << (key & 31);
                unsigned old = atomicOr(&d_bm2[key >> 5], bit);
                newe = !(old & bit);
            }
        }
        unsigned mball = __ballot_sync(0xffffffffu, newe);
        if (!mball) continue;
        int leader = __ffs(mball) - 1;
        int base = 0;
        if (lane == leader) base = atomicAdd(&d_ecnt2[0], __popc(mball));
        base = __shfl_sync(0xffffffffu, base, leader);
        if (newe){
            int ofs = __popc(mball & ((1u << lane) - 1u));
            d_er3[base + ofs] = r3;
            d_ec3[base + ofs] = c3;
        }
    }
}

__global__ void k_m3(){
    int nE = d_ecnt2[0];
    float mx = 0.f;
    for (int e = blockIdx.x*blockDim.x + threadIdx.x; e < nE; e += gridDim.x*blockDim.x){
        int r = d_er3[e], c = d_ec3[e];
        float dx = d_pos3[2*c]   - d_pos3[2*r];
        float dy = d_pos3[2*c+1] - d_pos3[2*r+1];
        mx = fmaxf(mx, fmaxf(fabsf(dx), fabsf(dy)));
    }
    warpMaxAtomic(mx, &d_m[2]);
}

__global__ void k_fillB3(){
    int nE = d_ecnt2[0];
    float inv = 1.f / (2.f * d_m[2] + 1e-12f);
    for (int e = blockIdx.x*blockDim.x + threadIdx.x; e < nE; e += gridDim.x*blockDim.x){
        int r = d_er3[e], c = d_ec3[e];
        int g = r >> 4;
        float psx = (d_pos3[2*c]   - d_pos3[2*r])   * inv + 0.5f;
        float psy = (d_pos3[2*c+1] - d_pos3[2*r+1]) * inv + 0.5f;
        int ix, iy; float fx, fy;
        spline_corners(psx, psy, ix, iy, fx, fy);
        float wxs[2] = {1.f-fx, fx}, wys[2] = {1.f-fy, fy};
        int rl = r & 15, cl = c & 15;
        #pragma unroll
        for (int sx=0; sx<2; sx++)
            #pragma unroll
            for (int sy=0; sy<2; sy++){
                int idx = (ix+sx)*5 + (iy+sy);
                d_B3[((g*KK + idx)*16 + rl)*16 + cl] = wxs[sx]*wys[sy];
            }
        atomicAdd(&d_deg3[r], 1.f);
    }
}

// acc3[g,r,k,i] = sum_c B3[g,k,r,c] * x3[g,c,i] — block per (g,k)
__global__ void k_bgemm3(){
    __shared__ float Bs3[16][17];
    __shared__ float xs3[16][64];
    int g = blockIdx.x / KK;
    int k = blockIdx.x % KK;
    size_t bbase = (size_t)blockIdx.x * 256;
    int t = threadIdx.x;
    if (t < 64){
        int r = t >> 2, c4 = (t & 3) * 4;
        float4 v = *(const float4*)&d_B3[bbase + r*16 + c4];
        Bs3[r][c4+0]=v.x; Bs3[r][c4+1]=v.y; Bs3[r][c4+2]=v.z; Bs3[r][c4+3]=v.w;
    }
    {
        int c = t >> 4, i4 = (t & 15) * 4;
        *(float4*)&xs3[c][i4] = *(const float4*)&d_x3[(g*16 + c)*F2 + i4];
    }
    __syncthreads();
    int r = t >> 4, i4 = (t & 15) * 4;
    float4 acc = make_float4(0.f,0.f,0.f,0.f);
    #pragma unroll
    for (int c = 0; c < 16; c++){
        float b = Bs3[r][c];
        float4 xv = *(const float4*)&xs3[c][i4];
        acc.x += b*xv.x; acc.y += b*xv.y; acc.z += b*xv.z; acc.w += b*xv.w;
    }
    *(float4*)&d_acc3[((long)(g*16 + r))*(KK*F2) + k*F2 + i4] = acc;
}

// ---------------- readout ----------------
__global__ void k_readout(const float* __restrict__ fcw, const float* __restrict__ fcb,
                          float* __restrict__ out){
    int g = blockIdx.x, t = threadIdx.x;     // 128 threads
    __shared__ float sf[F3];
    __shared__ float slg[10];
    float s = 0.f, cnt = 0.f;
    for (int j = 0; j < 16; j++){
        int n = g*16 + j;
        float nv = d_cnt2[n] > 0.f ? 1.f : 0.f;
        cnt += nv;
        s += nv * d_h3[n*F3 + t];
    }
    sf[t] = s / fmaxf(cnt, 1.f);
    __syncthreads();
    if (t < 10){
        float l = fcb[t];
        for (int i = 0; i < F3; i++) l += sf[i] * fcw[i*10 + t];
        slg[t] = l;
    }
    __syncthreads();
    if (t == 0){
        float mx = slg[0];
        for (int o = 1; o < 10; o++) mx = fmaxf(mx, slg[o]);
        float se = 0.f;
        for (int o = 0; o < 10; o++) se += expf(slg[o] - mx);
        float lse = logf(se) + mx;
        for (int o = 0; o < 10; o++) out[g*10 + o] = slg[o] - lse;
    }
}

// ---------------- launch ----------------
extern "C" void kernel_launch(void* const* d_in, const int* in_sizes, int n_in,
                              void* d_out, int out_size){
    const float* x    = (const float*)d_in[0];
    const float* pos  = (const float*)d_in[1];
    const int*   ei   = (const int*)  d_in[2];
    const float* W1   = (const float*)d_in[4];
    const float* r1   = (const float*)d_in[5];
    const float* b1   = (const float*)d_in[6];
    const float* W2   = (const float*)d_in[7];
    const float* r2p  = (const float*)d_in[8];
    const float* b2   = (const float*)d_in[9];
    const float* W3   = (const float*)d_in[10];
    const float* r3p  = (const float*)d_in[11];
    const float* b3   = (const float*)d_in[12];
    const float* fcw  = (const float*)d_in[13];
    const float* fcb  = (const float*)d_in[14];
    float* out = (float*)d_out;
    const int* row = ei;
    const int* col = ei + EE;

    k_init    <<<4096, 256>>>();
    k_m1      <<<1024, 256>>>(pos, row, col);
    k_scatter1<<<EE/256, 256>>>(pos, x, row, col);
    k_node1   <<<NN/8, 256>>>(x, W1, r1, b1);
    k_pool1   <<<NN/8, 256>>>(pos);
    k_fin1    <<<NC1*F1/256, 256>>>();
    k_remap1  <<<EE/256, 256>>>(pos, row, col);
    k_m2      <<<512, 256>>>();
    k_fillB2  <<<1024, 256>>>();
    k_bgemm2  <<<BG*KK, 256>>>();
    k_gemm2   <<<dim3(NC1/128, 1), 256>>>(W2, r2p, b2);
    k_pool2   <<<NC1/8, 256>>>();
    k_fin2    <<<NC2*F2/256, 256>>>();
    k_remap2  <<<512, 256>>>();
    k_m3      <<<128, 256>>>();
    k_fillB3  <<<128, 256>>>();
    k_bgemm3  <<<BG*KK, 256>>>();
    k_gemm3   <<<dim3(NC2/64, F3/64), 256>>>(W3, r3p, b3);
    k_readout <<<BG, 128>>>(fcw, fcb, out);
}